// round 15
// baseline (speedup 1.0000x reference)
#include <cuda_runtime.h>
#include <stdint.h>

#define N_PTS 16384
#define GS 64
#define NCELL (GS * GS * GS)           // 262144
#define CAP 16
#define OVCAP 1024
#define OX (-5.5f)
#define CELL_SZ 0.171875f              // 11/64
#define INV_CELL 5.8181818f            // 64/11
#define NB 128                         // persistent blocks (<= SM count: all resident)
#define TPB 256

#define FB_JT 512                      // db points per fallback j-split
#define FB_JS (N_PTS / FB_JT)          // 32

__device__ int    g_cnt[2][NCELL];              // per-cell count / slot cursor
__device__ float4 g_cell_pts[2][NCELL * CAP];   // per-cell storage (NOT zeroed: n-guards required)
__device__ float4 g_db[2][N_PTS];               // compact points, w = -0.5*|p|^2
__device__ int    g_ovcnt[2];
__device__ float4 g_ovpts[2][OVCAP];
__device__ int    g_nf[2];                      // fallback counts
__device__ int    g_flist[2][N_PTS];            // fallback query indices
__device__ unsigned int g_res[2][N_PTS];        // per-query min sq dist (float bits)
__device__ int    g_bar_cnt;                    // barrier arrivals (returns to 0)
__device__ int    g_bar_gen;                    // barrier generation (monotonic)

__device__ __forceinline__ void grid_barrier() {
    __threadfence();            // make this thread's writes visible
    __syncthreads();
    __shared__ int sgen;
    if (threadIdx.x == 0) {
        int gen = *(volatile int*)&g_bar_gen;
        int prev = atomicAdd(&g_bar_cnt, 1);
        if (prev == NB - 1) {
            g_bar_cnt = 0;
            __threadfence();
            atomicAdd(&g_bar_gen, 1);
        } else {
            while (*(volatile int*)&g_bar_gen == gen) { }
        }
        sgen = 0;               // dummy store to keep sgen live
    }
    __syncthreads();
    __threadfence();            // acquire side
    (void)0;
}

__device__ __forceinline__ unsigned long long pack2(float lo, float hi) {
    unsigned long long r;
    asm("mov.b64 %0, {%1, %2};" : "=l"(r) : "f"(lo), "f"(hi));
    return r;
}
__device__ __forceinline__ unsigned long long fma2(
    unsigned long long a, unsigned long long b, unsigned long long c) {
    unsigned long long d;
    asm("fma.rn.f32x2 %0, %1, %2, %3;" : "=l"(d) : "l"(a), "l"(b), "l"(c));
    return d;
}
__device__ __forceinline__ void unpack2(unsigned long long v, float& lo, float& hi) {
    asm("mov.b64 {%0, %1}, %2;" : "=f"(lo), "=f"(hi) : "l"(v));
}

__device__ __forceinline__ int cell_coord(float v) {
    int c = (int)floorf((v - OX) * INV_CELL);
    return min(max(c, 0), GS - 1);
}

// Margin from q to outside box [c-r, c+r]^3. Grid-edge faces hold all clamped
// points beyond the domain -> +inf margin on those sides.
__device__ __forceinline__ float box_margin(
    float qx, float qy, float qz, int cx, int cy, int cz, int r)
{
    float mxlo = (cx - r <= 0)      ? 1e30f : qx - (OX + (float)(cx - r) * CELL_SZ);
    float mxhi = (cx + r >= GS - 1) ? 1e30f : (OX + (float)(cx + r + 1) * CELL_SZ) - qx;
    float mylo = (cy - r <= 0)      ? 1e30f : qy - (OX + (float)(cy - r) * CELL_SZ);
    float myhi = (cy + r >= GS - 1) ? 1e30f : (OX + (float)(cy + r + 1) * CELL_SZ) - qy;
    float mzlo = (cz - r <= 0)      ? 1e30f : qz - (OX + (float)(cz - r) * CELL_SZ);
    float mzhi = (cz + r >= GS - 1) ? 1e30f : (OX + (float)(cz + r + 1) * CELL_SZ) - qz;
    float m = fminf(fminf(fminf(mxlo, mxhi), fminf(mylo, myhi)), fminf(mzlo, mzhi));
    return fmaxf(m, 0.0f);
}

__global__ void __launch_bounds__(TPB) cd_fused(
    const float* __restrict__ pred, const float* __restrict__ gt,
    float* __restrict__ out)
{
    const int tid  = blockIdx.x * TPB + threadIdx.x;   // 0..32767 exactly
    const int lane = threadIdx.x & 31;

    // ================= phase 0: zero counters =================
    {
        int4* c = (int4*)g_cnt;                        // 2*NCELL ints = 131072 int4
        for (int k = tid; k < (2 * NCELL) / 4; k += NB * TPB)
            c[k] = make_int4(0, 0, 0, 0);
        if (tid == 0) { g_ovcnt[0] = 0; g_ovcnt[1] = 0; g_nf[0] = 0; g_nf[1] = 0; }
    }
    grid_barrier();

    // ================= phase 1: build =================
    {
        int dir = tid >> 14;
        int i = tid & (N_PTS - 1);
        const float* P = dir ? pred : gt;              // dir0 db=gt, dir1 db=pred
        float x = P[3 * i], y = P[3 * i + 1], z = P[3 * i + 2];
        float c = -0.5f * fmaf(x, x, fmaf(y, y, z * z));
        g_db[dir][i] = make_float4(x, y, z, c);
        int cx = cell_coord(x), cy = cell_coord(y), cz = cell_coord(z);
        int cell = (cz * GS + cy) * GS + cx;
        int slot = atomicAdd(&g_cnt[dir][cell], 1);
        if (slot < CAP) {
            g_cell_pts[dir][cell * CAP + slot] = make_float4(x, y, z, 0.0f);
        } else {
            int o = atomicAdd(&g_ovcnt[dir], 1);
            if (o < OVCAP) g_ovpts[dir][o] = make_float4(x, y, z, 0.0f);
        }
    }
    grid_barrier();

    // ================= phase 2: query (one warp per query) =================
    {
        const int warp0 = tid >> 5;                    // 0..1023
        for (int wq = warp0; wq < 2 * N_PTS; wq += (NB * TPB) / 32) {
            const int dir = wq >> 14;
            const int i = wq & (N_PTS - 1);
            const float* Q = dir ? gt : pred;
            const float qx = Q[3 * i], qy = Q[3 * i + 1], qz = Q[3 * i + 2];
            const int cx = cell_coord(qx), cy = cell_coord(qy), cz = cell_coord(qz);
            const int*    __restrict__ cnts = g_cnt[dir];
            const float4* __restrict__ pts  = g_cell_pts[dir];

            float best_l = 3.402823466e+38f;

            // r=1 probe: lanes 0..26 cover the 3x3x3 box
            {
                int dz = lane / 9;
                int rem = lane - dz * 9;
                int dy = rem / 3;
                int dx = rem - dy * 3;
                int z = cz - 1 + dz, y = cy - 1 + dy, x = cx - 1 + dx;
                bool valid = (lane < 27) && (unsigned)z < GS && (unsigned)y < GS && (unsigned)x < GS;
                int cell = valid ? (z * GS + y) * GS + x : 0;
                int n = valid ? min(cnts[cell], CAP) : 0;
                const float4* row = pts + cell * CAP;
                // speculative first-4 loads; contents may be stale -> MUST stay n-guarded
                float4 p0 = row[0], p1 = row[1], p2 = row[2], p3 = row[3];
                float ddx, ddy, ddz;
                ddx = qx - p0.x; ddy = qy - p0.y; ddz = qz - p0.z;
                float d0 = fmaf(ddx, ddx, fmaf(ddy, ddy, ddz * ddz));
                ddx = qx - p1.x; ddy = qy - p1.y; ddz = qz - p1.z;
                float d1 = fmaf(ddx, ddx, fmaf(ddy, ddy, ddz * ddz));
                ddx = qx - p2.x; ddy = qy - p2.y; ddz = qz - p2.z;
                float d2 = fmaf(ddx, ddx, fmaf(ddy, ddy, ddz * ddz));
                ddx = qx - p3.x; ddy = qy - p3.y; ddz = qz - p3.z;
                float d3 = fmaf(ddx, ddx, fmaf(ddy, ddy, ddz * ddz));
                if (n > 0) best_l = fminf(best_l, d0);
                if (n > 1) best_l = fminf(best_l, d1);
                if (n > 2) best_l = fminf(best_l, d2);
                if (n > 3) best_l = fminf(best_l, d3);
                for (int k = 4; k < n; ++k) {
                    float4 p = row[k];
                    ddx = qx - p.x; ddy = qy - p.y; ddz = qz - p.z;
                    best_l = fminf(best_l, fmaf(ddx, ddx, fmaf(ddy, ddy, ddz * ddz)));
                }
            }

            float bw = best_l;
            for (int o = 16; o > 0; o >>= 1)
                bw = fminf(bw, __shfl_xor_sync(0xFFFFFFFFu, bw, o));
            float m1 = box_margin(qx, qy, qz, cx, cy, cz, 1);
            bool certified = (bw <= m1 * m1);

            // r=2 shell (98 cells) for the uncertified tail
            if (!certified) {
                for (int base = 0; base < 125; base += 32) {
                    int ci = base + lane;
                    if (ci < 125) {
                        int dz = ci / 25;
                        int rem = ci - dz * 25;
                        int dy = rem / 5;
                        int dx = rem - dy * 5;
                        int cheb = max(max(abs(dz - 2), abs(dy - 2)), abs(dx - 2));
                        int z = cz - 2 + dz, y = cy - 2 + dy, x = cx - 2 + dx;
                        bool ok = (cheb == 2) &&
                                  (unsigned)z < GS && (unsigned)y < GS && (unsigned)x < GS;
                        if (ok) {
                            int cell = (z * GS + y) * GS + x;
                            int n = min(cnts[cell], CAP);
                            const float4* row = pts + cell * CAP;
                            for (int k = 0; k < n; ++k) {
                                float4 p = row[k];
                                float ddx = qx - p.x, ddy = qy - p.y, ddz = qz - p.z;
                                best_l = fminf(best_l, fmaf(ddx, ddx, fmaf(ddy, ddy, ddz * ddz)));
                            }
                        }
                    }
                }
                bw = best_l;
                for (int o = 16; o > 0; o >>= 1)
                    bw = fminf(bw, __shfl_xor_sync(0xFFFFFFFFu, bw, o));
                float m2 = box_margin(qx, qy, qz, cx, cy, cz, 2);
                certified = (bw <= m2 * m2);
            }

            if (certified) {
                best_l = bw;
                int on = min(g_ovcnt[dir], OVCAP);
                for (int k = lane; k < on; k += 32) {
                    float4 p = g_ovpts[dir][k];
                    float ddx = qx - p.x, ddy = qy - p.y, ddz = qz - p.z;
                    best_l = fminf(best_l, fmaf(ddx, ddx, fmaf(ddy, ddy, ddz * ddz)));
                }
                for (int o = 16; o > 0; o >>= 1)
                    best_l = fminf(best_l, __shfl_xor_sync(0xFFFFFFFFu, best_l, o));
                if (lane == 0) g_res[dir][i] = __float_as_uint(fmaxf(best_l, 0.0f));
            } else {
                if (lane == 0) {
                    g_res[dir][i] = __float_as_uint(fmaxf(bw, 0.0f));
                    int pos = atomicAdd(&g_nf[dir], 1);
                    g_flist[dir][pos] = i;
                }
            }
        }
    }
    grid_barrier();

    // ================= phase 3: batched brute over fallback set =================
    // block b: dir=(b>>5)&1, jsplit=b&31, chunk base=(b>>6), chunks step 2 (covers 0..7).
    {
        __shared__ ulonglong2 tile_xy[FB_JT / 2];
        __shared__ ulonglong2 tile_zc[FB_JT / 2];
        const int jsplit = blockIdx.x & 31;
        const int dir    = (blockIdx.x >> 5) & 1;
        const int chunk0 = (blockIdx.x >> 6);           // 0 or 1
        const int nf = g_nf[dir];
        if (chunk0 * 256 < nf || (chunk0 + 2) * 256 < nf || true) {
            const int jb = jsplit * FB_JT;
            const float4* __restrict__ db = g_db[dir];
            if (threadIdx.x < FB_JT / 2) {
                float4 a = db[jb + 2 * threadIdx.x];
                float4 b = db[jb + 2 * threadIdx.x + 1];
                tile_xy[threadIdx.x] = make_ulonglong2(pack2(a.x, b.x), pack2(a.y, b.y));
                tile_zc[threadIdx.x] = make_ulonglong2(pack2(a.z, b.z), pack2(a.w, b.w));
            }
            __syncthreads();
            for (int chunk = chunk0; chunk < 8; chunk += 2) {
                const int q = chunk * 256 + threadIdx.x;
                if (q < nf) {
                    const int i = g_flist[dir][q];
                    const float* Q = dir ? gt : pred;
                    const float qx = Q[3 * i], qy = Q[3 * i + 1], qz = Q[3 * i + 2];
                    const unsigned long long pqx = pack2(qx, qx);
                    const unsigned long long pqy = pack2(qy, qy);
                    const unsigned long long pqz = pack2(qz, qz);
                    float best0 = -3.402823466e+38f, best1 = -3.402823466e+38f;
#pragma unroll 8
                    for (int k = 0; k < FB_JT / 2; ++k) {
                        const ulonglong2 xy = tile_xy[k];
                        const ulonglong2 zc = tile_zc[k];
                        unsigned long long tt = fma2(pqx, xy.x, zc.y);
                        tt = fma2(pqy, xy.y, tt);
                        tt = fma2(pqz, zc.x, tt);
                        float t0, t1;
                        unpack2(tt, t0, t1);
                        best0 = fmaxf(best0, t0);
                        best1 = fmaxf(best1, t1);
                    }
                    float bmax = fmaxf(best0, best1);
                    float q2 = fmaf(qx, qx, fmaf(qy, qy, qz * qz));
                    float d2 = fmaxf(fmaf(-2.0f, bmax, q2), 0.0f);
                    atomicMin(&g_res[dir][i], __float_as_uint(d2));
                }
            }
        }
    }
    grid_barrier();

    // ================= phase 4: final reduction (block 0) =================
    if (blockIdx.x == 0) {
        const unsigned int* r = (const unsigned int*)g_res;
        float s = 0.0f;
        for (int k = threadIdx.x; k < 2 * N_PTS; k += TPB)
            s += sqrtf(__uint_as_float(r[k]));
        for (int o = 16; o > 0; o >>= 1) s += __shfl_xor_sync(0xFFFFFFFFu, s, o);
        __shared__ float ssum[TPB / 32];
        if (lane == 0) ssum[threadIdx.x >> 5] = s;
        __syncthreads();
        if (threadIdx.x == 0) {
            float tot = 0.0f;
#pragma unroll
            for (int w = 0; w < TPB / 32; ++w) tot += ssum[w];
            out[0] = tot / (float)N_PTS;   // (sum_pred + sum_gt)/N = mean1 + mean2
        }
    }
}

extern "C" void kernel_launch(void* const* d_in, const int* in_sizes, int n_in,
                              void* d_out, int out_size) {
    const float* pred = (const float*)d_in[0];
    const float* gt   = (const float*)d_in[1];
    float* out = (float*)d_out;
    cd_fused<<<NB, TPB>>>(pred, gt, out);
}

// round 16
// speedup vs baseline: 2.1346x; 2.1346x over previous
#include <cuda_runtime.h>
#include <stdint.h>

#define N_PTS 16384
#define GS 64
#define NCELL (GS * GS * GS)           // 262144
#define CAP 16
#define OVCAP 1024
#define OX (-5.5f)
#define CELL_SZ 0.171875f              // 11/64
#define INV_CELL 5.8181818f            // 64/11
#define NB 128                         // persistent blocks (<= SM count: all resident)
#define TPB 1024
#define NTHREADS (NB * TPB)            // 131072
#define NWARPS (NTHREADS / 32)         // 4096

#define FB_JT 512                      // db points per fallback j-split
#define FB_JS (N_PTS / FB_JT)          // 32

__device__ int    g_cnt[2][NCELL];              // per-cell count / slot cursor
__device__ float4 g_cell_pts[2][NCELL * CAP];   // per-cell storage (NOT zeroed: n-guards required)
__device__ float4 g_db[2][N_PTS];               // compact points, w = -0.5*|p|^2
__device__ int    g_ovcnt[2];
__device__ float4 g_ovpts[2][OVCAP];
__device__ int    g_nf[2];                      // fallback counts
__device__ int    g_flist[2][N_PTS];            // fallback query indices
__device__ unsigned int g_res[2][N_PTS];        // per-query min sq dist (float bits)
__device__ int    g_bar_cnt;                    // barrier arrivals (returns to 0)
__device__ int    g_bar_gen;                    // barrier generation (monotonic)

__device__ __forceinline__ void grid_barrier() {
    __threadfence();            // release: make this block's writes visible
    __syncthreads();
    if (threadIdx.x == 0) {
        int gen = *(volatile int*)&g_bar_gen;
        int prev = atomicAdd(&g_bar_cnt, 1);
        if (prev == NB - 1) {
            g_bar_cnt = 0;
            __threadfence();
            atomicAdd(&g_bar_gen, 1);
        } else {
            while (*(volatile int*)&g_bar_gen == gen) { }
        }
    }
    __syncthreads();
    __threadfence();            // acquire side
}

__device__ __forceinline__ unsigned long long pack2(float lo, float hi) {
    unsigned long long r;
    asm("mov.b64 %0, {%1, %2};" : "=l"(r) : "f"(lo), "f"(hi));
    return r;
}
__device__ __forceinline__ unsigned long long fma2(
    unsigned long long a, unsigned long long b, unsigned long long c) {
    unsigned long long d;
    asm("fma.rn.f32x2 %0, %1, %2, %3;" : "=l"(d) : "l"(a), "l"(b), "l"(c));
    return d;
}
__device__ __forceinline__ void unpack2(unsigned long long v, float& lo, float& hi) {
    asm("mov.b64 {%0, %1}, %2;" : "=f"(lo), "=f"(hi) : "l"(v));
}

__device__ __forceinline__ int cell_coord(float v) {
    int c = (int)floorf((v - OX) * INV_CELL);
    return min(max(c, 0), GS - 1);
}

// Margin from q to outside box [c-r, c+r]^3. Grid-edge faces hold all clamped
// points beyond the domain -> +inf margin on those sides.
__device__ __forceinline__ float box_margin(
    float qx, float qy, float qz, int cx, int cy, int cz, int r)
{
    float mxlo = (cx - r <= 0)      ? 1e30f : qx - (OX + (float)(cx - r) * CELL_SZ);
    float mxhi = (cx + r >= GS - 1) ? 1e30f : (OX + (float)(cx + r + 1) * CELL_SZ) - qx;
    float mylo = (cy - r <= 0)      ? 1e30f : qy - (OX + (float)(cy - r) * CELL_SZ);
    float myhi = (cy + r >= GS - 1) ? 1e30f : (OX + (float)(cy + r + 1) * CELL_SZ) - qy;
    float mzlo = (cz - r <= 0)      ? 1e30f : qz - (OX + (float)(cz - r) * CELL_SZ);
    float mzhi = (cz + r >= GS - 1) ? 1e30f : (OX + (float)(cz + r + 1) * CELL_SZ) - qz;
    float m = fminf(fminf(fminf(mxlo, mxhi), fminf(mylo, myhi)), fminf(mzlo, mzhi));
    return fmaxf(m, 0.0f);
}

__global__ void __launch_bounds__(TPB, 1) cd_fused(
    const float* __restrict__ pred, const float* __restrict__ gt,
    float* __restrict__ out)
{
    const int tid  = blockIdx.x * TPB + threadIdx.x;   // 0..131071
    const int lane = threadIdx.x & 31;

    // ================= phase 0: zero counters =================
    {
        int4* c = (int4*)g_cnt;                        // 2*NCELL ints = 131072 int4
        if (tid < (2 * NCELL) / 4) c[tid] = make_int4(0, 0, 0, 0);
        if (tid == 0) { g_ovcnt[0] = 0; g_ovcnt[1] = 0; g_nf[0] = 0; g_nf[1] = 0; }
    }
    grid_barrier();

    // ================= phase 1: build =================
    if (tid < 2 * N_PTS) {
        int dir = tid >> 14;
        int i = tid & (N_PTS - 1);
        const float* P = dir ? pred : gt;              // dir0 db=gt, dir1 db=pred
        float x = P[3 * i], y = P[3 * i + 1], z = P[3 * i + 2];
        float c = -0.5f * fmaf(x, x, fmaf(y, y, z * z));
        g_db[dir][i] = make_float4(x, y, z, c);
        int cx = cell_coord(x), cy = cell_coord(y), cz = cell_coord(z);
        int cell = (cz * GS + cy) * GS + cx;
        int slot = atomicAdd(&g_cnt[dir][cell], 1);
        if (slot < CAP) {
            g_cell_pts[dir][cell * CAP + slot] = make_float4(x, y, z, 0.0f);
        } else {
            int o = atomicAdd(&g_ovcnt[dir], 1);
            if (o < OVCAP) g_ovpts[dir][o] = make_float4(x, y, z, 0.0f);
        }
    }
    grid_barrier();

    // ================= phase 2: query (one warp per query, 8 queries/warp) =================
    {
        const int warp0 = tid >> 5;                    // 0..4095
        for (int wq = warp0; wq < 2 * N_PTS; wq += NWARPS) {
            const int dir = wq >> 14;
            const int i = wq & (N_PTS - 1);
            const float* Q = dir ? gt : pred;
            const float qx = Q[3 * i], qy = Q[3 * i + 1], qz = Q[3 * i + 2];
            const int cx = cell_coord(qx), cy = cell_coord(qy), cz = cell_coord(qz);
            const int*    __restrict__ cnts = g_cnt[dir];
            const float4* __restrict__ pts  = g_cell_pts[dir];

            float best_l = 3.402823466e+38f;

            // r=1 probe: lanes 0..26 cover the 3x3x3 box
            {
                int dz = lane / 9;
                int rem = lane - dz * 9;
                int dy = rem / 3;
                int dx = rem - dy * 3;
                int z = cz - 1 + dz, y = cy - 1 + dy, x = cx - 1 + dx;
                bool valid = (lane < 27) && (unsigned)z < GS && (unsigned)y < GS && (unsigned)x < GS;
                int cell = valid ? (z * GS + y) * GS + x : 0;
                int n = valid ? min(cnts[cell], CAP) : 0;
                const float4* row = pts + cell * CAP;
                // speculative first-4 loads; contents may be stale -> MUST stay n-guarded
                float4 p0 = row[0], p1 = row[1], p2 = row[2], p3 = row[3];
                float ddx, ddy, ddz;
                ddx = qx - p0.x; ddy = qy - p0.y; ddz = qz - p0.z;
                float d0 = fmaf(ddx, ddx, fmaf(ddy, ddy, ddz * ddz));
                ddx = qx - p1.x; ddy = qy - p1.y; ddz = qz - p1.z;
                float d1 = fmaf(ddx, ddx, fmaf(ddy, ddy, ddz * ddz));
                ddx = qx - p2.x; ddy = qy - p2.y; ddz = qz - p2.z;
                float d2 = fmaf(ddx, ddx, fmaf(ddy, ddy, ddz * ddz));
                ddx = qx - p3.x; ddy = qy - p3.y; ddz = qz - p3.z;
                float d3 = fmaf(ddx, ddx, fmaf(ddy, ddy, ddz * ddz));
                if (n > 0) best_l = fminf(best_l, d0);
                if (n > 1) best_l = fminf(best_l, d1);
                if (n > 2) best_l = fminf(best_l, d2);
                if (n > 3) best_l = fminf(best_l, d3);
                for (int k = 4; k < n; ++k) {
                    float4 p = row[k];
                    ddx = qx - p.x; ddy = qy - p.y; ddz = qz - p.z;
                    best_l = fminf(best_l, fmaf(ddx, ddx, fmaf(ddy, ddy, ddz * ddz)));
                }
            }

            float bw = best_l;
            for (int o = 16; o > 0; o >>= 1)
                bw = fminf(bw, __shfl_xor_sync(0xFFFFFFFFu, bw, o));
            float m1 = box_margin(qx, qy, qz, cx, cy, cz, 1);
            bool certified = (bw <= m1 * m1);

            // r=2 shell (98 cells) for the uncertified tail
            if (!certified) {
                for (int base = 0; base < 125; base += 32) {
                    int ci = base + lane;
                    if (ci < 125) {
                        int dz = ci / 25;
                        int rem = ci - dz * 25;
                        int dy = rem / 5;
                        int dx = rem - dy * 5;
                        int cheb = max(max(abs(dz - 2), abs(dy - 2)), abs(dx - 2));
                        int z = cz - 2 + dz, y = cy - 2 + dy, x = cx - 2 + dx;
                        bool ok = (cheb == 2) &&
                                  (unsigned)z < GS && (unsigned)y < GS && (unsigned)x < GS;
                        if (ok) {
                            int cell = (z * GS + y) * GS + x;
                            int n = min(cnts[cell], CAP);
                            const float4* row = pts + cell * CAP;
                            for (int k = 0; k < n; ++k) {
                                float4 p = row[k];
                                float ddx = qx - p.x, ddy = qy - p.y, ddz = qz - p.z;
                                best_l = fminf(best_l, fmaf(ddx, ddx, fmaf(ddy, ddy, ddz * ddz)));
                            }
                        }
                    }
                }
                bw = best_l;
                for (int o = 16; o > 0; o >>= 1)
                    bw = fminf(bw, __shfl_xor_sync(0xFFFFFFFFu, bw, o));
                float m2 = box_margin(qx, qy, qz, cx, cy, cz, 2);
                certified = (bw <= m2 * m2);
            }

            if (certified) {
                best_l = bw;
                int on = min(g_ovcnt[dir], OVCAP);
                for (int k = lane; k < on; k += 32) {
                    float4 p = g_ovpts[dir][k];
                    float ddx = qx - p.x, ddy = qy - p.y, ddz = qz - p.z;
                    best_l = fminf(best_l, fmaf(ddx, ddx, fmaf(ddy, ddy, ddz * ddz)));
                }
                for (int o = 16; o > 0; o >>= 1)
                    best_l = fminf(best_l, __shfl_xor_sync(0xFFFFFFFFu, best_l, o));
                if (lane == 0) g_res[dir][i] = __float_as_uint(fmaxf(best_l, 0.0f));
            } else {
                if (lane == 0) {
                    g_res[dir][i] = __float_as_uint(fmaxf(bw, 0.0f));
                    int pos = atomicAdd(&g_nf[dir], 1);
                    g_flist[dir][pos] = i;
                }
            }
        }
    }
    grid_barrier();

    // ================= phase 3: batched brute over fallback set =================
    // block b: dir=b&1, jsplit=(b>>1)&31, chunk=b>>6 (0..1). 1024 queries/chunk.
    {
        __shared__ ulonglong2 tile_xy[FB_JT / 2];
        __shared__ ulonglong2 tile_zc[FB_JT / 2];
        const int dir    = blockIdx.x & 1;
        const int jsplit = (blockIdx.x >> 1) & 31;
        const int chunk  = blockIdx.x >> 6;             // 0 or 1
        const int nf = g_nf[dir];
        const int q = chunk * TPB + threadIdx.x;        // covers 2048 per dir
        const int jb = jsplit * FB_JT;
        const float4* __restrict__ db = g_db[dir];
        if (threadIdx.x < FB_JT / 2) {
            float4 a = db[jb + 2 * threadIdx.x];
            float4 b = db[jb + 2 * threadIdx.x + 1];
            tile_xy[threadIdx.x] = make_ulonglong2(pack2(a.x, b.x), pack2(a.y, b.y));
            tile_zc[threadIdx.x] = make_ulonglong2(pack2(a.z, b.z), pack2(a.w, b.w));
        }
        __syncthreads();
        if (q < nf) {
            const int i = g_flist[dir][q];
            const float* Q = dir ? gt : pred;
            const float qx = Q[3 * i], qy = Q[3 * i + 1], qz = Q[3 * i + 2];
            const unsigned long long pqx = pack2(qx, qx);
            const unsigned long long pqy = pack2(qy, qy);
            const unsigned long long pqz = pack2(qz, qz);
            float best0 = -3.402823466e+38f, best1 = -3.402823466e+38f;
#pragma unroll 8
            for (int k = 0; k < FB_JT / 2; ++k) {
                const ulonglong2 xy = tile_xy[k];
                const ulonglong2 zc = tile_zc[k];
                unsigned long long tt = fma2(pqx, xy.x, zc.y);
                tt = fma2(pqy, xy.y, tt);
                tt = fma2(pqz, zc.x, tt);
                float t0, t1;
                unpack2(tt, t0, t1);
                best0 = fmaxf(best0, t0);
                best1 = fmaxf(best1, t1);
            }
            float bmax = fmaxf(best0, best1);
            float q2 = fmaf(qx, qx, fmaf(qy, qy, qz * qz));
            float d2 = fmaxf(fmaf(-2.0f, bmax, q2), 0.0f);
            atomicMin(&g_res[dir][i], __float_as_uint(d2));
        }
    }
    grid_barrier();

    // ================= phase 4: final reduction (block 0) =================
    if (blockIdx.x == 0) {
        const unsigned int* r = (const unsigned int*)g_res;
        float s = 0.0f;
        for (int k = threadIdx.x; k < 2 * N_PTS; k += TPB)
            s += sqrtf(__uint_as_float(r[k]));
        for (int o = 16; o > 0; o >>= 1) s += __shfl_xor_sync(0xFFFFFFFFu, s, o);
        __shared__ float ssum[TPB / 32];
        if (lane == 0) ssum[threadIdx.x >> 5] = s;
        __syncthreads();
        if (threadIdx.x == 0) {
            float tot = 0.0f;
#pragma unroll
            for (int w = 0; w < TPB / 32; ++w) tot += ssum[w];
            out[0] = tot / (float)N_PTS;   // (sum_pred + sum_gt)/N = mean1 + mean2
        }
    }
}

extern "C" void kernel_launch(void* const* d_in, const int* in_sizes, int n_in,
                              void* d_out, int out_size) {
    const float* pred = (const float*)d_in[0];
    const float* gt   = (const float*)d_in[1];
    float* out = (float*)d_out;
    cd_fused<<<NB, TPB>>>(pred, gt, out);
}